// round 12
// baseline (speedup 1.0000x reference)
#include <cuda_runtime.h>
#include <cuda_bf16.h>
#include <cstdint>

#define BATCH 4
#define NCLS 19
#define IMH 512
#define IMW 1024
#define HW (IMH * IMW)           // 524288 = 2^19
#define NPIX (BATCH * HW)
#define KTOP 256
#define EPSF 1e-6f

// ---------------- scratch (static device arrays; no allocation) ----------------
__device__ float         g_entropy[NPIX];
__device__ unsigned char g_label[NPIX];
__device__ float         g_score[NPIX];
__device__ unsigned int  g_cand[NPIX];            // compacted boundary-bin bits
__device__ unsigned int  g_hist0[BATCH * 2048];
__device__ unsigned int  g_histB[BATCH * 2048];
__device__ float         g_fsB  [BATCH * 2048];
__device__ unsigned int  g_histC[BATCH * 1024];
__device__ float         g_fsC  [BATCH * 1024];
__device__ unsigned int  g_sel_key[BATCH];        // level-0 bin (top 11 bits)
__device__ unsigned int  g_sel_k[BATCH];          // remaining k inside level-0 bin
__device__ unsigned int  g_keyB[BATCH];
__device__ unsigned int  g_k2[BATCH];
__device__ float         g_tailB[BATCH];
__device__ float         g_sum[BATCH];            // sum of values with prefix > key0
__device__ unsigned int  g_ncand[BATCH];
__device__ unsigned int  g_ctr0[BATCH];           // region last-block counter
__device__ unsigned int  g_ctrA[BATCH], g_ctrB[BATCH], g_ctrC[BATCH];
__device__ unsigned int  g_flagB[BATCH];

// ---------------- block-wide descending radix-select -------------------------
template<int T, bool LDCG>
__device__ __forceinline__ void block_select(const unsigned int* __restrict__ h,
                                             int nbins, unsigned int k, int tid,
                                             unsigned int* s_scan,      // >= T/32
                                             unsigned int* ret_bin,
                                             unsigned int* ret_rem) {
    const int W = T / 32;
    int cs = nbins / T;
    int base = nbins - 1 - tid * cs;
    unsigned int csum = 0;
    for (int i = 0; i < cs; i++) csum += LDCG ? __ldcg(&h[base - i]) : h[base - i];

    unsigned int v = csum;
    #pragma unroll
    for (int off = 1; off < 32; off <<= 1) {
        unsigned int y = __shfl_up_sync(0xFFFFFFFFu, v, off);
        if ((tid & 31) >= off) v += y;
    }
    if ((tid & 31) == 31) s_scan[tid >> 5] = v;
    __syncthreads();
    if (tid < W) {
        unsigned int w = s_scan[tid];
        const unsigned int m = (W == 32) ? 0xFFFFFFFFu : ((1u << W) - 1u);
        #pragma unroll
        for (int off = 1; off < W; off <<= 1) {
            unsigned int y = __shfl_up_sync(m, w, off);
            if (tid >= off) w += y;
        }
        s_scan[tid] = w;
    }
    __syncthreads();
    unsigned int incl = v + ((tid >= 32) ? s_scan[(tid >> 5) - 1] : 0u);
    unsigned int excl = incl - csum;

    if (excl < k && k <= incl) {
        unsigned int run = excl;
        for (int i = 0; i < cs; i++) {
            unsigned int hv = LDCG ? __ldcg(&h[base - i]) : h[base - i];
            if (run < k && k <= run + hv) {
                *ret_bin = (unsigned int)(base - i);
                *ret_rem = k - run;
                break;
            }
            run += hv;
        }
    }
}

// ---------------- kernel 1: per-pixel entropy + argmax (float4, fused init) ----
__global__ void k_pixel(const float* __restrict__ logit) {
    if (blockIdx.x == 0) {
        int t = threadIdx.x;
        for (int i = t; i < 2048 * BATCH; i += 256) { g_hist0[i] = 0; g_histB[i] = 0; g_fsB[i] = 0.0f; }
        for (int i = t; i < 1024 * BATCH; i += 256) { g_histC[i] = 0; g_fsC[i] = 0.0f; }
        if (t < BATCH) {
            g_sum[t] = 0.0f; g_ncand[t] = 0;
            g_ctr0[t] = 0; g_ctrA[t] = 0; g_ctrB[t] = 0; g_ctrC[t] = 0;
            g_flagB[t] = 0;
        }
    }

    int idx = blockIdx.x * blockDim.x + threadIdx.x;   // one float4 (4 pixels)
    int p4 = idx * 4;
    int b  = p4 >> 19;
    int hw = p4 & (HW - 1);
    const float4* base = (const float4*)(logit + (size_t)b * NCLS * HW + hw);
    const int planeStride = HW / 4;

    float4 ent  = make_float4(0.f, 0.f, 0.f, 0.f);
    float4 best = make_float4(-1.f, -1.f, -1.f, -1.f);
    int bc0 = 0, bc1 = 0, bc2 = 0, bc3 = 0;
    #pragma unroll
    for (int c = 0; c < NCLS; c++) {
        float4 p = base[c * planeStride];
        ent.x -= p.x * __logf(p.x + EPSF);
        ent.y -= p.y * __logf(p.y + EPSF);
        ent.z -= p.z * __logf(p.z + EPSF);
        ent.w -= p.w * __logf(p.w + EPSF);
        if (p.x > best.x) { best.x = p.x; bc0 = c; }
        if (p.y > best.y) { best.y = p.y; bc1 = c; }
        if (p.z > best.z) { best.z = p.z; bc2 = c; }
        if (p.w > best.w) { best.w = p.w; bc3 = c; }
    }
    float invLogC = 1.0f / __logf((float)NCLS);
    ent.x *= invLogC; ent.y *= invLogC; ent.z *= invLogC; ent.w *= invLogC;
    ((float4*)g_entropy)[idx] = ent;
    ((uchar4*)g_label)[idx] = make_uchar4((unsigned char)bc0, (unsigned char)bc1,
                                          (unsigned char)bc2, (unsigned char)bc3);
}

// ---------------- kernel 2: 3x3 region score + hist0 + fused select0 ----------
#define TBX 32
#define TBY 8
__global__ void k_region(void) {
    __shared__ float         s_ent[TBY + 2][TBX + 2];
    __shared__ unsigned char s_lab[TBY + 2][TBX + 2];
    __shared__ unsigned int  s_hist[2048];
    __shared__ float         s_T2[48];          // T2[nIdx*16+c] = log(c/n+eps)/logC
    __shared__ unsigned int  s_scan[8];
    __shared__ unsigned int  s_bin, s_rem;
    __shared__ int           s_last;

    int b  = blockIdx.z;
    int bx = blockIdx.x * TBX;
    int by = blockIdx.y * TBY;
    int tx = threadIdx.x, ty = threadIdx.y;
    int tid = ty * TBX + tx;

    for (int i = tid; i < 2048; i += 256) s_hist[i] = 0;

    if (tid < 48) {
        int nIdx = tid >> 4, c = tid & 15;
        float n = (nIdx == 0) ? 4.0f : (nIdx == 1) ? 6.0f : 9.0f;
        float val = 0.0f;
        if (c >= 1 && c <= 9)
            val = __logf((float)c / n + EPSF) * (1.0f / __logf((float)NCLS));
        s_T2[tid] = val;
    }

    bool interior = (blockIdx.x > 0) & (blockIdx.x < gridDim.x - 1) &
                    (blockIdx.y > 0) & (blockIdx.y < gridDim.y - 1);

    const int TILE = (TBY + 2) * (TBX + 2);
    if (interior) {
        for (int i = tid; i < TILE; i += 256) {
            int ly = i / (TBX + 2), lx = i % (TBX + 2);
            int gidx = b * HW + (by + ly - 1) * IMW + (bx + lx - 1);
            s_ent[ly][lx] = g_entropy[gidx];
            s_lab[ly][lx] = g_label[gidx];
        }
    } else {
        for (int i = tid; i < TILE; i += 256) {
            int ly = i / (TBX + 2), lx = i % (TBX + 2);
            int gy = by + ly - 1, gx = bx + lx - 1;
            bool ok = (gy >= 0 && gy < IMH && gx >= 0 && gx < IMW);
            int gidx = b * HW + gy * IMW + gx;
            s_ent[ly][lx] = ok ? g_entropy[gidx] : 0.0f;
            s_lab[ly][lx] = ok ? g_label[gidx] : (unsigned char)255;
        }
    }
    __syncthreads();

    float entsum = 0.0f;
    unsigned long long acc0 = 0ull;   // classes 0..15, 4-bit counters
    unsigned int acc1 = 0u;           // classes 16..18
    int labv[9];
    float imp, sc;

    if (interior) {
        #pragma unroll
        for (int dy = 0; dy < 3; dy++)
        #pragma unroll
            for (int dx = 0; dx < 3; dx++) {
                entsum += s_ent[ty + dy][tx + dx];
                int L = s_lab[ty + dy][tx + dx];
                labv[dy * 3 + dx] = L;
                unsigned long long bit = 1ull << ((L & 15) * 4);
                if (L < 16) acc0 += bit; else acc1 += (unsigned int)bit;
            }
        float simp = 0.0f;
        #pragma unroll
        for (int i = 0; i < 9; i++) {
            int L = labv[i];
            unsigned long long a = (L < 16) ? acc0 : (unsigned long long)acc1;
            int c = (int)((a >> ((L & 15) * 4)) & 15ull);
            simp += s_T2[32 + c];               // nIdx=2 (n=9)
        }
        imp = -(1.0f / 9.0f) * simp;
        sc  = entsum * (1.0f / 9.0f) * imp;
    } else {
        int n = 0;
        #pragma unroll
        for (int dy = 0; dy < 3; dy++)
        #pragma unroll
            for (int dx = 0; dx < 3; dx++) {
                entsum += s_ent[ty + dy][tx + dx];
                int L = s_lab[ty + dy][tx + dx];
                labv[dy * 3 + dx] = L;
                if (L != 255) {
                    n++;
                    unsigned long long bit = 1ull << ((L & 15) * 4);
                    if (L < 16) acc0 += bit; else acc1 += (unsigned int)bit;
                }
            }
        int nIdx = (n == 9) ? 2 : ((n == 6) ? 1 : 0);
        float invn = 1.0f / (float)n;
        float simp = 0.0f;
        #pragma unroll
        for (int i = 0; i < 9; i++) {
            int L = labv[i];
            if (L != 255) {
                unsigned long long a = (L < 16) ? acc0 : (unsigned long long)acc1;
                int c = (int)((a >> ((L & 15) * 4)) & 15ull);
                simp += s_T2[nIdx * 16 + c];
            }
        }
        imp = -invn * simp;
        sc  = entsum * (1.0f / 9.0f) * imp;
    }

    g_score[b * HW + (by + ty) * IMW + (bx + tx)] = sc;

    // hist0: warp-aggregated smem atomic (scores concentrated -> hot bins)
    unsigned int bits = __float_as_uint(sc);     // sc >= 0 => uint order == float order
    unsigned int bin = bits >> 21;
    unsigned int peers = __match_any_sync(0xFFFFFFFFu, bin);
    int leader = __ffs(peers) - 1;
    if ((tid & 31) == leader) atomicAdd(&s_hist[bin], (unsigned int)__popc(peers));
    __syncthreads();
    for (int i = tid; i < 2048; i += 256) {
        unsigned int v = s_hist[i];
        if (v) atomicAdd(&g_hist0[b * 2048 + i], v);
    }

    __threadfence();
    __syncthreads();
    if (tid == 0) {
        unsigned int done = atomicAdd(&g_ctr0[b], 1u);
        s_last = (done == gridDim.x * gridDim.y - 1);
    }
    __syncthreads();
    if (s_last) {
        block_select<256, true>(g_hist0 + b * 2048, 2048, KTOP, tid,
                                s_scan, &s_bin, &s_rem);
        __syncthreads();
        if (tid == 0) { g_sel_key[b] = s_bin; g_sel_k[b] = s_rem; }
    }
}

// ---------------- kernel 3: persistent top-k (one score scan + cand phases) ----
#define PB 128   // blocks per batch (512 total, co-resident on 148 SMs)
#define PT 256
__global__ void __launch_bounds__(PT) k_topk(float* __restrict__ out) {
    __shared__ unsigned int s_buf[4096];      // per-block candidate staging (16KB)
    __shared__ unsigned int s_n, s_base;
    __shared__ unsigned int s_scan[PT / 32];
    __shared__ float        s_wsum[PT / 32];
    __shared__ unsigned int s_bin, s_rem;
    __shared__ int s_last;

    int b = blockIdx.y;
    int tid = threadIdx.x;
    int lane = tid & 31;
    unsigned int key0 = __ldcg(&g_sel_key[b]);
    const float4* sc = (const float4*)(g_score + b * HW);
    unsigned int* cand = g_cand + b * HW;

    if (tid == 0) s_n = 0;
    __syncthreads();

    // ---- phase A: scan scores; sum prefix>key0; compact prefix==key0 ----
    float gsum = 0.0f;
    const int TPB = PB * PT;                 // 32768 threads/batch
    int base = blockIdx.x * PT + tid;
    #pragma unroll
    for (int it = 0; it < 4; it++) {         // 4 * 32768 = 131072 = HW/4
        float4 v = sc[base + it * TPB];
        float val[4] = { v.x, v.y, v.z, v.w };
        #pragma unroll
        for (int j = 0; j < 4; j++) {
            unsigned int bits = __float_as_uint(val[j]);
            unsigned int pref = bits >> 21;
            if (pref > key0) gsum += val[j];
            bool eq = (pref == key0);
            unsigned int m = __ballot_sync(0xFFFFFFFFu, eq);
            if (m) {
                int leader = __ffs(m) - 1;
                unsigned int wb;
                if (lane == leader) wb = atomicAdd(&s_n, (unsigned int)__popc(m));
                wb = __shfl_sync(0xFFFFFFFFu, wb, leader);
                if (eq) s_buf[wb + __popc(m & ((1u << lane) - 1u))] = bits;
            }
        }
    }
    #pragma unroll
    for (int off = 16; off > 0; off >>= 1)
        gsum += __shfl_down_sync(0xFFFFFFFFu, gsum, off);
    if (lane == 0) s_wsum[tid >> 5] = gsum;
    __syncthreads();
    if (tid == 0) {
        float bs = 0.0f;
        #pragma unroll
        for (int w = 0; w < PT / 32; w++) bs += s_wsum[w];
        if (bs != 0.0f) atomicAdd(&g_sum[b], bs);
        s_base = atomicAdd(&g_ncand[b], s_n);
    }
    __syncthreads();
    for (unsigned int i = tid; i < s_n; i += PT) cand[s_base + i] = s_buf[i];

    // ---- barrier A (all 128 blocks of this batch) ----
    __threadfence();
    __syncthreads();
    if (tid == 0) {
        atomicAdd(&g_ctrA[b], 1u);
        while (atomicAdd(&g_ctrA[b], 0u) < PB) __nanosleep(64);
    }
    __syncthreads();

    unsigned int ncand = __ldcg(&g_ncand[b]);

    // ---- phase B: hist+fsum over bits[20:10] of candidates ----
    for (unsigned int i = blockIdx.x * PT + tid; i < ncand; i += PB * PT) {
        unsigned int bits = __ldcg(&cand[i]);
        unsigned int bn = (bits >> 10) & 0x7FFu;
        atomicAdd(&g_histB[b * 2048 + bn], 1u);
        atomicAdd(&g_fsB[b * 2048 + bn], __uint_as_float(bits));
    }
    __threadfence();
    __syncthreads();
    if (tid == 0) {
        unsigned int done = atomicAdd(&g_ctrB[b], 1u);
        s_last = (done == PB - 1);
    }
    __syncthreads();
    if (s_last) {
        unsigned int k1 = __ldcg(&g_sel_k[b]);
        block_select<PT, true>(g_histB + b * 2048, 2048, k1, tid, s_scan, &s_bin, &s_rem);
        __syncthreads();
        unsigned int keyB = s_bin, k2v = s_rem;
        float tail = 0.0f;
        for (int i = tid; i < 2048; i += PT)
            if ((unsigned int)i > keyB) tail += __ldcg(&g_fsB[b * 2048 + i]);
        #pragma unroll
        for (int off = 16; off > 0; off >>= 1)
            tail += __shfl_down_sync(0xFFFFFFFFu, tail, off);
        if (lane == 0) s_wsum[tid >> 5] = tail;
        __syncthreads();
        if (tid == 0) {
            float ts = 0.0f;
            #pragma unroll
            for (int w = 0; w < PT / 32; w++) ts += s_wsum[w];
            g_keyB[b] = keyB; g_k2[b] = k2v; g_tailB[b] = ts;
            __threadfence();
            atomicExch(&g_flagB[b], 1u);
        }
        __syncthreads();
    } else {
        if (tid == 0) { while (atomicAdd(&g_flagB[b], 0u) == 0u) __nanosleep(64); }
        __syncthreads();
    }

    unsigned int keyB = __ldcg(&g_keyB[b]);

    // ---- phase C: hist+fsum over bits[9:0] within B-bin ----
    for (unsigned int i = blockIdx.x * PT + tid; i < ncand; i += PB * PT) {
        unsigned int bits = __ldcg(&cand[i]);
        if (((bits >> 10) & 0x7FFu) == keyB) {
            unsigned int bn = bits & 0x3FFu;
            atomicAdd(&g_histC[b * 1024 + bn], 1u);
            atomicAdd(&g_fsC[b * 1024 + bn], __uint_as_float(bits));
        }
    }
    __threadfence();
    __syncthreads();
    if (tid == 0) {
        unsigned int done = atomicAdd(&g_ctrC[b], 1u);
        s_last = (done == PB - 1);
    }
    __syncthreads();
    if (!s_last) return;

    // ---- last block: select C + finalize ----
    unsigned int k2 = __ldcg(&g_k2[b]);
    block_select<PT, true>(g_histC + b * 1024, 1024, k2, tid, s_scan, &s_bin, &s_rem);
    __syncthreads();
    unsigned int binC = s_bin, rem = s_rem;
    float tailC = 0.0f;
    for (int i = tid; i < 1024; i += PT)
        if ((unsigned int)i > binC) tailC += __ldcg(&g_fsC[b * 1024 + i]);
    #pragma unroll
    for (int off = 16; off > 0; off >>= 1)
        tailC += __shfl_down_sync(0xFFFFFFFFu, tailC, off);
    if (lane == 0) s_wsum[tid >> 5] = tailC;
    __syncthreads();
    if (tid == 0) {
        float tc = 0.0f;
        #pragma unroll
        for (int w = 0; w < PT / 32; w++) tc += s_wsum[w];
        float vstar = __uint_as_float((key0 << 21) | (keyB << 10) | binC);
        out[b] = __ldcg(&g_sum[b]) + __ldcg(&g_tailB[b]) + tc + (float)rem * vstar;
    }
}

// ---------------- launch ----------------
extern "C" void kernel_launch(void* const* d_in, const int* in_sizes, int n_in,
                              void* d_out, int out_size) {
    const float* logit = (const float*)d_in[0];
    float* out = (float*)d_out;

    k_pixel<<<NPIX / 4 / 256, 256>>>(logit);
    k_region<<<dim3(IMW / TBX, IMH / TBY, BATCH), dim3(TBX, TBY)>>>();
    k_topk<<<dim3(PB, BATCH), PT>>>(out);
}

// round 13
// speedup vs baseline: 1.0643x; 1.0643x over previous
#include <cuda_runtime.h>
#include <cuda_bf16.h>
#include <cstdint>

#define BATCH 4
#define NCLS 19
#define IMH 512
#define IMW 1024
#define HW (IMH * IMW)           // 524288 = 2^19
#define NPIX (BATCH * HW)
#define KTOP 256
#define EPSF 1e-6f

// ---------------- scratch (static device arrays; no allocation) ----------------
__device__ float         g_entropy[NPIX];
__device__ unsigned char g_label[NPIX];
__device__ float         g_score[NPIX];
__device__ unsigned int  g_cand[NPIX];            // compacted boundary-bin bits
__device__ unsigned int  g_hist0[BATCH * 2048];
__device__ unsigned int  g_histB[BATCH * 2048];
__device__ float         g_fsB  [BATCH * 2048];
__device__ unsigned int  g_sel_key[BATCH];        // level-0 bin (top 11 bits)
__device__ unsigned int  g_sel_k[BATCH];          // remaining k inside level-0 bin
__device__ float         g_sum[BATCH];            // sum of values with prefix > key0
__device__ unsigned int  g_ncand[BATCH];
__device__ unsigned int  g_ctr0[BATCH];           // region last-block counter
__device__ unsigned int  g_ctrA[BATCH];           // refine last-block counter

// ---------------- block-wide descending radix-select -------------------------
// Finds bin (scanning from highest down) where cumulative count crosses k.
// Exactly one thread writes *ret_bin/*ret_rem; caller must __syncthreads after.
template<int T, bool LDCG>
__device__ __forceinline__ void block_select(const unsigned int* __restrict__ h,
                                             int nbins, unsigned int k, int tid,
                                             unsigned int* s_scan,      // >= T/32
                                             unsigned int* ret_bin,
                                             unsigned int* ret_rem) {
    const int W = T / 32;
    int cs = nbins / T;
    int base = nbins - 1 - tid * cs;
    unsigned int csum = 0;
    for (int i = 0; i < cs; i++) csum += LDCG ? __ldcg(&h[base - i]) : h[base - i];

    unsigned int v = csum;
    #pragma unroll
    for (int off = 1; off < 32; off <<= 1) {
        unsigned int y = __shfl_up_sync(0xFFFFFFFFu, v, off);
        if ((tid & 31) >= off) v += y;
    }
    if ((tid & 31) == 31) s_scan[tid >> 5] = v;
    __syncthreads();
    if (tid < W) {
        unsigned int w = s_scan[tid];
        const unsigned int m = (W == 32) ? 0xFFFFFFFFu : ((1u << W) - 1u);
        #pragma unroll
        for (int off = 1; off < W; off <<= 1) {
            unsigned int y = __shfl_up_sync(m, w, off);
            if (tid >= off) w += y;
        }
        s_scan[tid] = w;
    }
    __syncthreads();
    unsigned int incl = v + ((tid >= 32) ? s_scan[(tid >> 5) - 1] : 0u);
    unsigned int excl = incl - csum;

    if (excl < k && k <= incl) {
        unsigned int run = excl;
        for (int i = 0; i < cs; i++) {
            unsigned int hv = LDCG ? __ldcg(&h[base - i]) : h[base - i];
            if (run < k && k <= run + hv) {
                *ret_bin = (unsigned int)(base - i);
                *ret_rem = k - run;
                break;
            }
            run += hv;
        }
    }
}

// ---------------- kernel 1: per-pixel entropy + argmax (float4, fused init) ----
__global__ void k_pixel(const float* __restrict__ logit) {
    if (blockIdx.x == 0) {
        int t = threadIdx.x;
        for (int i = t; i < 2048 * BATCH; i += 256) { g_hist0[i] = 0; g_histB[i] = 0; g_fsB[i] = 0.0f; }
        if (t < BATCH) {
            g_sum[t] = 0.0f; g_ncand[t] = 0;
            g_ctr0[t] = 0; g_ctrA[t] = 0;
        }
    }

    int idx = blockIdx.x * blockDim.x + threadIdx.x;   // one float4 (4 pixels)
    int p4 = idx * 4;
    int b  = p4 >> 19;
    int hw = p4 & (HW - 1);
    const float4* base = (const float4*)(logit + (size_t)b * NCLS * HW + hw);
    const int planeStride = HW / 4;

    float4 ent  = make_float4(0.f, 0.f, 0.f, 0.f);
    float4 best = make_float4(-1.f, -1.f, -1.f, -1.f);
    int bc0 = 0, bc1 = 0, bc2 = 0, bc3 = 0;
    #pragma unroll
    for (int c = 0; c < NCLS; c++) {
        float4 p = base[c * planeStride];
        ent.x -= p.x * __logf(p.x + EPSF);
        ent.y -= p.y * __logf(p.y + EPSF);
        ent.z -= p.z * __logf(p.z + EPSF);
        ent.w -= p.w * __logf(p.w + EPSF);
        if (p.x > best.x) { best.x = p.x; bc0 = c; }
        if (p.y > best.y) { best.y = p.y; bc1 = c; }
        if (p.z > best.z) { best.z = p.z; bc2 = c; }
        if (p.w > best.w) { best.w = p.w; bc3 = c; }
    }
    float invLogC = 1.0f / __logf((float)NCLS);
    ent.x *= invLogC; ent.y *= invLogC; ent.z *= invLogC; ent.w *= invLogC;
    ((float4*)g_entropy)[idx] = ent;
    ((uchar4*)g_label)[idx] = make_uchar4((unsigned char)bc0, (unsigned char)bc1,
                                          (unsigned char)bc2, (unsigned char)bc3);
}

// ---------------- kernel 2: 3x3 region score + hist0 + fused select0 ----------
#define TBX 32
#define TBY 8
__global__ void k_region(void) {
    __shared__ float         s_ent[TBY + 2][TBX + 2];
    __shared__ unsigned char s_lab[TBY + 2][TBX + 2];
    __shared__ unsigned int  s_hist[2048];
    __shared__ float         s_T2[48];          // T2[nIdx*16+c] = log(c/n+eps)/logC
    __shared__ unsigned int  s_scan[8];
    __shared__ unsigned int  s_bin, s_rem;
    __shared__ int           s_last;

    int b  = blockIdx.z;
    int bx = blockIdx.x * TBX;
    int by = blockIdx.y * TBY;
    int tx = threadIdx.x, ty = threadIdx.y;
    int tid = ty * TBX + tx;

    for (int i = tid; i < 2048; i += 256) s_hist[i] = 0;

    if (tid < 48) {
        int nIdx = tid >> 4, c = tid & 15;
        float n = (nIdx == 0) ? 4.0f : (nIdx == 1) ? 6.0f : 9.0f;
        float val = 0.0f;
        if (c >= 1 && c <= 9)
            val = __logf((float)c / n + EPSF) * (1.0f / __logf((float)NCLS));
        s_T2[tid] = val;
    }

    bool interior = (blockIdx.x > 0) & (blockIdx.x < gridDim.x - 1) &
                    (blockIdx.y > 0) & (blockIdx.y < gridDim.y - 1);

    const int TILE = (TBY + 2) * (TBX + 2);
    if (interior) {
        for (int i = tid; i < TILE; i += 256) {
            int ly = i / (TBX + 2), lx = i % (TBX + 2);
            int gidx = b * HW + (by + ly - 1) * IMW + (bx + lx - 1);
            s_ent[ly][lx] = g_entropy[gidx];
            s_lab[ly][lx] = g_label[gidx];
        }
    } else {
        for (int i = tid; i < TILE; i += 256) {
            int ly = i / (TBX + 2), lx = i % (TBX + 2);
            int gy = by + ly - 1, gx = bx + lx - 1;
            bool ok = (gy >= 0 && gy < IMH && gx >= 0 && gx < IMW);
            int gidx = b * HW + gy * IMW + gx;
            s_ent[ly][lx] = ok ? g_entropy[gidx] : 0.0f;
            s_lab[ly][lx] = ok ? g_label[gidx] : (unsigned char)255;
        }
    }
    __syncthreads();

    float entsum = 0.0f;
    unsigned long long acc0 = 0ull;   // classes 0..15, 4-bit counters
    unsigned int acc1 = 0u;           // classes 16..18
    int labv[9];
    float imp, sc;

    if (interior) {
        #pragma unroll
        for (int dy = 0; dy < 3; dy++)
        #pragma unroll
            for (int dx = 0; dx < 3; dx++) {
                entsum += s_ent[ty + dy][tx + dx];
                int L = s_lab[ty + dy][tx + dx];
                labv[dy * 3 + dx] = L;
                unsigned long long bit = 1ull << ((L & 15) * 4);
                if (L < 16) acc0 += bit; else acc1 += (unsigned int)bit;
            }
        float simp = 0.0f;
        #pragma unroll
        for (int i = 0; i < 9; i++) {
            int L = labv[i];
            unsigned long long a = (L < 16) ? acc0 : (unsigned long long)acc1;
            int c = (int)((a >> ((L & 15) * 4)) & 15ull);
            simp += s_T2[32 + c];               // nIdx=2 (n=9)
        }
        imp = -(1.0f / 9.0f) * simp;
        sc  = entsum * (1.0f / 9.0f) * imp;
    } else {
        int n = 0;
        #pragma unroll
        for (int dy = 0; dy < 3; dy++)
        #pragma unroll
            for (int dx = 0; dx < 3; dx++) {
                entsum += s_ent[ty + dy][tx + dx];
                int L = s_lab[ty + dy][tx + dx];
                labv[dy * 3 + dx] = L;
                if (L != 255) {
                    n++;
                    unsigned long long bit = 1ull << ((L & 15) * 4);
                    if (L < 16) acc0 += bit; else acc1 += (unsigned int)bit;
                }
            }
        int nIdx = (n == 9) ? 2 : ((n == 6) ? 1 : 0);
        float invn = 1.0f / (float)n;
        float simp = 0.0f;
        #pragma unroll
        for (int i = 0; i < 9; i++) {
            int L = labv[i];
            if (L != 255) {
                unsigned long long a = (L < 16) ? acc0 : (unsigned long long)acc1;
                int c = (int)((a >> ((L & 15) * 4)) & 15ull);
                simp += s_T2[nIdx * 16 + c];
            }
        }
        imp = -invn * simp;
        sc  = entsum * (1.0f / 9.0f) * imp;
    }

    g_score[b * HW + (by + ty) * IMW + (bx + tx)] = sc;

    // hist0: warp-aggregated smem atomic (scores concentrated -> hot bins)
    unsigned int bits = __float_as_uint(sc);     // sc >= 0 => uint order == float order
    unsigned int bin = bits >> 21;
    unsigned int peers = __match_any_sync(0xFFFFFFFFu, bin);
    int leader = __ffs(peers) - 1;
    if ((tid & 31) == leader) atomicAdd(&s_hist[bin], (unsigned int)__popc(peers));
    __syncthreads();
    for (int i = tid; i < 2048; i += 256) {
        unsigned int v = s_hist[i];
        if (v) atomicAdd(&g_hist0[b * 2048 + i], v);
    }

    __threadfence();
    __syncthreads();
    if (tid == 0) {
        unsigned int done = atomicAdd(&g_ctr0[b], 1u);
        s_last = (done == gridDim.x * gridDim.y - 1);
    }
    __syncthreads();
    if (s_last) {
        block_select<256, true>(g_hist0 + b * 2048, 2048, KTOP, tid,
                                s_scan, &s_bin, &s_rem);
        __syncthreads();
        if (tid == 0) { g_sel_key[b] = s_bin; g_sel_k[b] = s_rem; }
    }
}

// ---------------- kernel 3: one-scan refine (level1 hist+fsum+compact) --------
// Phase A (all blocks): scan scores; sum prefix>key0; for prefix==key0 build
//   SMEM hist+fsum over bits[20:10] and compact raw bits to g_cand.
// Last-done block: select-1, tailB, then solo level-2 over L2-hot candidates,
//   select-2, closed-form finalize. No global per-element atomics anywhere.
#define PB 128   // blocks per batch
#define PT 512
__global__ void __launch_bounds__(PT) k_refine(float* __restrict__ out) {
    __shared__ unsigned int s_cnt[2048];
    __shared__ float        s_fs[2048];
    __shared__ unsigned int s_buf[4096];      // candidate staging (block max = 4096)
    __shared__ unsigned int s_n, s_base;
    __shared__ unsigned int s_scan[PT / 32];
    __shared__ float        s_wsum[PT / 32];
    __shared__ unsigned int s_bin, s_rem;
    __shared__ int s_last;

    int b = blockIdx.y;
    int tid = threadIdx.x;
    int lane = tid & 31;
    unsigned int key0 = __ldcg(&g_sel_key[b]);
    const float4* sc = (const float4*)(g_score + b * HW);
    unsigned int* cand = g_cand + b * HW;

    for (int i = tid; i < 2048; i += PT) { s_cnt[i] = 0; s_fs[i] = 0.0f; }
    if (tid == 0) s_n = 0;
    __syncthreads();

    // ---- phase A ----
    float gsum = 0.0f;
    const int TPB = PB * PT;                 // 65536 threads/batch
    int base = blockIdx.x * PT + tid;
    #pragma unroll
    for (int it = 0; it < 2; it++) {         // 2 * 65536 = 131072 = HW/4
        float4 v = sc[base + it * TPB];
        float val[4] = { v.x, v.y, v.z, v.w };
        #pragma unroll
        for (int j = 0; j < 4; j++) {
            unsigned int bits = __float_as_uint(val[j]);
            unsigned int pref = bits >> 21;
            if (pref > key0) gsum += val[j];
            bool eq = (pref == key0);
            if (eq) {
                unsigned int bn = (bits >> 10) & 0x7FFu;
                atomicAdd(&s_cnt[bn], 1u);
                atomicAdd(&s_fs[bn], val[j]);
            }
            unsigned int m = __ballot_sync(0xFFFFFFFFu, eq);
            if (m) {
                int leader = __ffs(m) - 1;
                unsigned int wb;
                if (lane == leader) wb = atomicAdd(&s_n, (unsigned int)__popc(m));
                wb = __shfl_sync(0xFFFFFFFFu, wb, leader);
                if (eq) s_buf[wb + __popc(m & ((1u << lane) - 1u))] = bits;
            }
        }
    }
    // reduce gsum
    #pragma unroll
    for (int off = 16; off > 0; off >>= 1)
        gsum += __shfl_down_sync(0xFFFFFFFFu, gsum, off);
    if (lane == 0) s_wsum[tid >> 5] = gsum;
    __syncthreads();
    if (tid == 0) {
        float bs = 0.0f;
        #pragma unroll
        for (int w = 0; w < PT / 32; w++) bs += s_wsum[w];
        if (bs != 0.0f) atomicAdd(&g_sum[b], bs);
        s_base = atomicAdd(&g_ncand[b], s_n);
    }
    __syncthreads();
    // flush hist/fsum + candidates
    for (int i = tid; i < 2048; i += PT) {
        unsigned int c = s_cnt[i];
        if (c) { atomicAdd(&g_histB[b * 2048 + i], c); atomicAdd(&g_fsB[b * 2048 + i], s_fs[i]); }
    }
    for (unsigned int i = tid; i < s_n; i += PT) cand[s_base + i] = s_buf[i];

    __threadfence();
    __syncthreads();
    if (tid == 0) {
        unsigned int done = atomicAdd(&g_ctrA[b], 1u);
        s_last = (done == PB - 1);
    }
    __syncthreads();
    if (!s_last) return;

    // ---- last block: select-1 + tailB ----
    unsigned int k1 = __ldcg(&g_sel_k[b]);
    block_select<PT, true>(g_histB + b * 2048, 2048, k1, tid, s_scan, &s_bin, &s_rem);
    __syncthreads();
    unsigned int keyB = s_bin, k2 = s_rem;

    float tailB = 0.0f;
    for (int i = tid; i < 2048; i += PT)
        if ((unsigned int)i > keyB) tailB += __ldcg(&g_fsB[b * 2048 + i]);

    // ---- solo level-2 over candidates (smem hist+fsum, 4-way unrolled) ----
    __syncthreads();
    for (int i = tid; i < 1024; i += PT) { s_cnt[i] = 0; s_fs[i] = 0.0f; }
    __syncthreads();
    unsigned int ncand = __ldcg(&g_ncand[b]);
    unsigned int i0 = tid;
    for (; i0 + 3 * PT < ncand; i0 += 4 * PT) {
        unsigned int b0 = __ldcg(&cand[i0]);
        unsigned int b1 = __ldcg(&cand[i0 + PT]);
        unsigned int b2 = __ldcg(&cand[i0 + 2 * PT]);
        unsigned int b3 = __ldcg(&cand[i0 + 3 * PT]);
        if (((b0 >> 10) & 0x7FFu) == keyB) { atomicAdd(&s_cnt[b0 & 0x3FFu], 1u); atomicAdd(&s_fs[b0 & 0x3FFu], __uint_as_float(b0)); }
        if (((b1 >> 10) & 0x7FFu) == keyB) { atomicAdd(&s_cnt[b1 & 0x3FFu], 1u); atomicAdd(&s_fs[b1 & 0x3FFu], __uint_as_float(b1)); }
        if (((b2 >> 10) & 0x7FFu) == keyB) { atomicAdd(&s_cnt[b2 & 0x3FFu], 1u); atomicAdd(&s_fs[b2 & 0x3FFu], __uint_as_float(b2)); }
        if (((b3 >> 10) & 0x7FFu) == keyB) { atomicAdd(&s_cnt[b3 & 0x3FFu], 1u); atomicAdd(&s_fs[b3 & 0x3FFu], __uint_as_float(b3)); }
    }
    for (; i0 < ncand; i0 += PT) {
        unsigned int bx = __ldcg(&cand[i0]);
        if (((bx >> 10) & 0x7FFu) == keyB) { atomicAdd(&s_cnt[bx & 0x3FFu], 1u); atomicAdd(&s_fs[bx & 0x3FFu], __uint_as_float(bx)); }
    }
    __syncthreads();

    // ---- select-2 + tailC + finalize ----
    block_select<PT, false>(s_cnt, 1024, k2, tid, s_scan, &s_bin, &s_rem);
    __syncthreads();
    unsigned int binC = s_bin, rem = s_rem;

    float tailC = 0.0f;
    for (int i = tid; i < 1024; i += PT)
        if ((unsigned int)i > binC) tailC += s_fs[i];

    float tot = tailB + tailC;
    #pragma unroll
    for (int off = 16; off > 0; off >>= 1)
        tot += __shfl_down_sync(0xFFFFFFFFu, tot, off);
    if (lane == 0) s_wsum[tid >> 5] = tot;
    __syncthreads();
    if (tid == 0) {
        float ts = 0.0f;
        #pragma unroll
        for (int w = 0; w < PT / 32; w++) ts += s_wsum[w];
        // every value in binC has the exact bit pattern (key0<<21)|(keyB<<10)|binC
        float vstar = __uint_as_float((key0 << 21) | (keyB << 10) | binC);
        out[b] = __ldcg(&g_sum[b]) + ts + (float)rem * vstar;
    }
}

// ---------------- launch ----------------
extern "C" void kernel_launch(void* const* d_in, const int* in_sizes, int n_in,
                              void* d_out, int out_size) {
    const float* logit = (const float*)d_in[0];
    float* out = (float*)d_out;

    k_pixel<<<NPIX / 4 / 256, 256>>>(logit);
    k_region<<<dim3(IMW / TBX, IMH / TBY, BATCH), dim3(TBX, TBY)>>>();
    k_refine<<<dim3(PB, BATCH), PT>>>(out);
}

// round 14
// speedup vs baseline: 1.0907x; 1.0248x over previous
#include <cuda_runtime.h>
#include <cuda_bf16.h>
#include <cstdint>

#define BATCH 4
#define NCLS 19
#define IMH 512
#define IMW 1024
#define HW (IMH * IMW)           // 524288 = 2^19
#define NPIX (BATCH * HW)
#define KTOP 256
#define EPSF 1e-6f

// ---------------- scratch (static device arrays; no allocation) ----------------
__device__ float         g_entropy[NPIX];
__device__ unsigned char g_label[NPIX];
__device__ float         g_score[NPIX];
__device__ unsigned int  g_cand[NPIX];            // compacted boundary-bin bits
__device__ unsigned int  g_hist0[BATCH * 2048];
__device__ unsigned int  g_histB[BATCH * 2048];
__device__ float         g_fsB  [BATCH * 2048];
__device__ unsigned int  g_sel_key[BATCH];        // level-0 bin (top 11 bits)
__device__ unsigned int  g_sel_k[BATCH];          // remaining k inside level-0 bin
__device__ float         g_sum[BATCH];            // sum of values with prefix > key0
__device__ unsigned int  g_ncand[BATCH];
__device__ unsigned int  g_ctr0[BATCH];           // region last-block counter
__device__ unsigned int  g_ctrA[BATCH];           // refine last-block counter

// ---------------- block-wide descending radix-select -------------------------
// Finds bin (scanning from highest down) where cumulative count crosses k.
// Exactly one thread writes *ret_bin/*ret_rem; caller must __syncthreads after.
template<int T, bool LDCG>
__device__ __forceinline__ void block_select(const unsigned int* __restrict__ h,
                                             int nbins, unsigned int k, int tid,
                                             unsigned int* s_scan,      // >= T/32
                                             unsigned int* ret_bin,
                                             unsigned int* ret_rem) {
    const int W = T / 32;
    int cs = nbins / T;
    int base = nbins - 1 - tid * cs;
    unsigned int csum = 0;
    for (int i = 0; i < cs; i++) csum += LDCG ? __ldcg(&h[base - i]) : h[base - i];

    unsigned int v = csum;
    #pragma unroll
    for (int off = 1; off < 32; off <<= 1) {
        unsigned int y = __shfl_up_sync(0xFFFFFFFFu, v, off);
        if ((tid & 31) >= off) v += y;
    }
    if ((tid & 31) == 31) s_scan[tid >> 5] = v;
    __syncthreads();
    if (tid < W) {
        unsigned int w = s_scan[tid];
        const unsigned int m = (W == 32) ? 0xFFFFFFFFu : ((1u << W) - 1u);
        #pragma unroll
        for (int off = 1; off < W; off <<= 1) {
            unsigned int y = __shfl_up_sync(m, w, off);
            if (tid >= off) w += y;
        }
        s_scan[tid] = w;
    }
    __syncthreads();
    unsigned int incl = v + ((tid >= 32) ? s_scan[(tid >> 5) - 1] : 0u);
    unsigned int excl = incl - csum;

    if (excl < k && k <= incl) {
        unsigned int run = excl;
        for (int i = 0; i < cs; i++) {
            unsigned int hv = LDCG ? __ldcg(&h[base - i]) : h[base - i];
            if (run < k && k <= run + hv) {
                *ret_bin = (unsigned int)(base - i);
                *ret_rem = k - run;
                break;
            }
            run += hv;
        }
    }
}

// ---------------- kernel 1: per-pixel entropy + argmax (float4, fused init) ----
__global__ void k_pixel(const float* __restrict__ logit) {
    if (blockIdx.x == 0) {
        int t = threadIdx.x;
        for (int i = t; i < 2048 * BATCH; i += 256) { g_hist0[i] = 0; g_histB[i] = 0; g_fsB[i] = 0.0f; }
        if (t < BATCH) {
            g_sum[t] = 0.0f; g_ncand[t] = 0;
            g_ctr0[t] = 0; g_ctrA[t] = 0;
        }
    }

    int idx = blockIdx.x * blockDim.x + threadIdx.x;   // one float4 (4 pixels)
    int p4 = idx * 4;
    int b  = p4 >> 19;
    int hw = p4 & (HW - 1);
    const float4* base = (const float4*)(logit + (size_t)b * NCLS * HW + hw);
    const int planeStride = HW / 4;

    float4 ent  = make_float4(0.f, 0.f, 0.f, 0.f);
    float4 best = make_float4(-1.f, -1.f, -1.f, -1.f);
    int bc0 = 0, bc1 = 0, bc2 = 0, bc3 = 0;
    #pragma unroll
    for (int c = 0; c < NCLS; c++) {
        float4 p = base[c * planeStride];
        ent.x -= p.x * __logf(p.x + EPSF);
        ent.y -= p.y * __logf(p.y + EPSF);
        ent.z -= p.z * __logf(p.z + EPSF);
        ent.w -= p.w * __logf(p.w + EPSF);
        if (p.x > best.x) { best.x = p.x; bc0 = c; }
        if (p.y > best.y) { best.y = p.y; bc1 = c; }
        if (p.z > best.z) { best.z = p.z; bc2 = c; }
        if (p.w > best.w) { best.w = p.w; bc3 = c; }
    }
    float invLogC = 1.0f / __logf((float)NCLS);
    ent.x *= invLogC; ent.y *= invLogC; ent.z *= invLogC; ent.w *= invLogC;
    ((float4*)g_entropy)[idx] = ent;
    ((uchar4*)g_label)[idx] = make_uchar4((unsigned char)bc0, (unsigned char)bc1,
                                          (unsigned char)bc2, (unsigned char)bc3);
}

// ---------------- kernel 2: 3x3 region score + hist0 + fused select0 ----------
// (reverted to the R11 known-good version: fixed-shift nibble-table impurity,
//  uniform halo path, plain smem atomic for hist0)
#define TBX 32
#define TBY 8
__global__ void k_region(void) {
    __shared__ float         s_ent[TBY + 2][TBX + 2];
    __shared__ unsigned char s_lab[TBY + 2][TBX + 2];
    __shared__ unsigned int  s_hist[2048];
    __shared__ float         s_T[48];           // impurity table: [nIdx*16 + count]
    __shared__ unsigned int  s_scan[8];
    __shared__ unsigned int  s_bin, s_rem;
    __shared__ int           s_last;

    int b  = blockIdx.z;
    int bx = blockIdx.x * TBX;
    int by = blockIdx.y * TBY;
    int tx = threadIdx.x, ty = threadIdx.y;
    int tid = ty * TBX + tx;

    for (int i = tid; i < 2048; i += 256) s_hist[i] = 0;

    // impurity lookup table: T[nIdx][c] = -(c/n)*log(c/n+eps)/logC, n in {4,6,9}
    if (tid < 48) {
        int nIdx = tid >> 4, c = tid & 15;
        float n = (nIdx == 0) ? 4.0f : (nIdx == 1) ? 6.0f : 9.0f;
        float val = 0.0f;
        if (c >= 1 && c <= 9) {
            float p = (float)c / n;
            val = -p * __logf(p + EPSF) * (1.0f / __logf((float)NCLS));
        }
        s_T[tid] = val;
    }

    // halo tile load
    const int TILE = (TBY + 2) * (TBX + 2);
    for (int i = tid; i < TILE; i += 256) {
        int ly = i / (TBX + 2), lx = i % (TBX + 2);
        int gy = by + ly - 1, gx = bx + lx - 1;
        bool ok = (gy >= 0 && gy < IMH && gx >= 0 && gx < IMW);
        int gidx = b * HW + gy * IMW + gx;
        s_ent[ly][lx] = ok ? g_entropy[gidx] : 0.0f;
        s_lab[ly][lx] = ok ? g_label[gidx] : (unsigned char)255;
    }
    __syncthreads();

    // 3x3 gather: entropy sum + nibble-packed class counts
    float entsum = 0.0f;
    unsigned long long accLo = 0ull;   // classes 0..15, 4-bit counters
    unsigned int accHi = 0u;           // classes 16..18
    int n = 0;
    #pragma unroll
    for (int dy = 0; dy < 3; dy++)
    #pragma unroll
        for (int dx = 0; dx < 3; dx++) {
            entsum += s_ent[ty + dy][tx + dx];
            int L = s_lab[ty + dy][tx + dx];
            if (L < 16)        { accLo += 1ull << (L * 4);        n++; }
            else if (L != 255) { accHi += 1u   << ((L - 16) * 4); n++; }
        }

    int nIdx = (n == 9) ? 2 : ((n == 6) ? 1 : 0);
    const float* T = s_T + nIdx * 16;
    float imp = 0.0f;
    #pragma unroll
    for (int c = 0; c < 16; c++) imp += T[(unsigned int)(accLo >> (c * 4)) & 15u];
    #pragma unroll
    for (int c = 0; c < 3; c++)  imp += T[(accHi >> (c * 4)) & 15u];

    float sc = entsum * (1.0f / 9.0f) * imp;
    g_score[b * HW + (by + ty) * IMW + (bx + tx)] = sc;

    unsigned int bits = __float_as_uint(sc);     // sc >= 0 => uint order == float order
    atomicAdd(&s_hist[bits >> 21], 1u);
    __syncthreads();
    for (int i = tid; i < 2048; i += 256) {
        unsigned int v = s_hist[i];
        if (v) atomicAdd(&g_hist0[b * 2048 + i], v);
    }

    __threadfence();
    __syncthreads();
    if (tid == 0) {
        unsigned int done = atomicAdd(&g_ctr0[b], 1u);
        s_last = (done == gridDim.x * gridDim.y - 1);
    }
    __syncthreads();
    if (s_last) {
        block_select<256, true>(g_hist0 + b * 2048, 2048, KTOP, tid,
                                s_scan, &s_bin, &s_rem);
        __syncthreads();
        if (tid == 0) { g_sel_key[b] = s_bin; g_sel_k[b] = s_rem; }
    }
}

// ---------------- kernel 3: one-scan refine (level1 hist+fsum+compact) --------
// Phase A (all blocks): scan scores; sum prefix>key0; for prefix==key0 build
//   SMEM hist+fsum over bits[20:10] and compact raw bits to g_cand.
// Last-done block: select-1, tailB, then solo level-2 over L2-hot candidates,
//   select-2, closed-form finalize. No global per-element atomics anywhere.
#define PB 128   // blocks per batch
#define PT 512
__global__ void __launch_bounds__(PT) k_refine(float* __restrict__ out) {
    __shared__ unsigned int s_cnt[2048];
    __shared__ float        s_fs[2048];
    __shared__ unsigned int s_buf[4096];      // candidate staging (block max = 4096)
    __shared__ unsigned int s_n, s_base;
    __shared__ unsigned int s_scan[PT / 32];
    __shared__ float        s_wsum[PT / 32];
    __shared__ unsigned int s_bin, s_rem;
    __shared__ int s_last;

    int b = blockIdx.y;
    int tid = threadIdx.x;
    int lane = tid & 31;
    unsigned int key0 = __ldcg(&g_sel_key[b]);
    const float4* sc = (const float4*)(g_score + b * HW);
    unsigned int* cand = g_cand + b * HW;

    for (int i = tid; i < 2048; i += PT) { s_cnt[i] = 0; s_fs[i] = 0.0f; }
    if (tid == 0) s_n = 0;
    __syncthreads();

    // ---- phase A ----
    float gsum = 0.0f;
    const int TPB = PB * PT;                 // 65536 threads/batch
    int base = blockIdx.x * PT + tid;
    #pragma unroll
    for (int it = 0; it < 2; it++) {         // 2 * 65536 = 131072 = HW/4
        float4 v = sc[base + it * TPB];
        float val[4] = { v.x, v.y, v.z, v.w };
        #pragma unroll
        for (int j = 0; j < 4; j++) {
            unsigned int bits = __float_as_uint(val[j]);
            unsigned int pref = bits >> 21;
            if (pref > key0) gsum += val[j];
            bool eq = (pref == key0);
            if (eq) {
                unsigned int bn = (bits >> 10) & 0x7FFu;
                atomicAdd(&s_cnt[bn], 1u);
                atomicAdd(&s_fs[bn], val[j]);
            }
            unsigned int m = __ballot_sync(0xFFFFFFFFu, eq);
            if (m) {
                int leader = __ffs(m) - 1;
                unsigned int wb;
                if (lane == leader) wb = atomicAdd(&s_n, (unsigned int)__popc(m));
                wb = __shfl_sync(0xFFFFFFFFu, wb, leader);
                if (eq) s_buf[wb + __popc(m & ((1u << lane) - 1u))] = bits;
            }
        }
    }
    // reduce gsum
    #pragma unroll
    for (int off = 16; off > 0; off >>= 1)
        gsum += __shfl_down_sync(0xFFFFFFFFu, gsum, off);
    if (lane == 0) s_wsum[tid >> 5] = gsum;
    __syncthreads();
    if (tid == 0) {
        float bs = 0.0f;
        #pragma unroll
        for (int w = 0; w < PT / 32; w++) bs += s_wsum[w];
        if (bs != 0.0f) atomicAdd(&g_sum[b], bs);
        s_base = atomicAdd(&g_ncand[b], s_n);
    }
    __syncthreads();
    // flush hist/fsum + candidates
    for (int i = tid; i < 2048; i += PT) {
        unsigned int c = s_cnt[i];
        if (c) { atomicAdd(&g_histB[b * 2048 + i], c); atomicAdd(&g_fsB[b * 2048 + i], s_fs[i]); }
    }
    for (unsigned int i = tid; i < s_n; i += PT) cand[s_base + i] = s_buf[i];

    __threadfence();
    __syncthreads();
    if (tid == 0) {
        unsigned int done = atomicAdd(&g_ctrA[b], 1u);
        s_last = (done == PB - 1);
    }
    __syncthreads();
    if (!s_last) return;

    // ---- last block: select-1 + tailB ----
    unsigned int k1 = __ldcg(&g_sel_k[b]);
    block_select<PT, true>(g_histB + b * 2048, 2048, k1, tid, s_scan, &s_bin, &s_rem);
    __syncthreads();
    unsigned int keyB = s_bin, k2 = s_rem;

    float tailB = 0.0f;
    for (int i = tid; i < 2048; i += PT)
        if ((unsigned int)i > keyB) tailB += __ldcg(&g_fsB[b * 2048 + i]);

    // ---- solo level-2 over candidates (smem hist+fsum, 4-way unrolled) ----
    __syncthreads();
    for (int i = tid; i < 1024; i += PT) { s_cnt[i] = 0; s_fs[i] = 0.0f; }
    __syncthreads();
    unsigned int ncand = __ldcg(&g_ncand[b]);
    unsigned int i0 = tid;
    for (; i0 + 3 * PT < ncand; i0 += 4 * PT) {
        unsigned int b0 = __ldcg(&cand[i0]);
        unsigned int b1 = __ldcg(&cand[i0 + PT]);
        unsigned int b2 = __ldcg(&cand[i0 + 2 * PT]);
        unsigned int b3 = __ldcg(&cand[i0 + 3 * PT]);
        if (((b0 >> 10) & 0x7FFu) == keyB) { atomicAdd(&s_cnt[b0 & 0x3FFu], 1u); atomicAdd(&s_fs[b0 & 0x3FFu], __uint_as_float(b0)); }
        if (((b1 >> 10) & 0x7FFu) == keyB) { atomicAdd(&s_cnt[b1 & 0x3FFu], 1u); atomicAdd(&s_fs[b1 & 0x3FFu], __uint_as_float(b1)); }
        if (((b2 >> 10) & 0x7FFu) == keyB) { atomicAdd(&s_cnt[b2 & 0x3FFu], 1u); atomicAdd(&s_fs[b2 & 0x3FFu], __uint_as_float(b2)); }
        if (((b3 >> 10) & 0x7FFu) == keyB) { atomicAdd(&s_cnt[b3 & 0x3FFu], 1u); atomicAdd(&s_fs[b3 & 0x3FFu], __uint_as_float(b3)); }
    }
    for (; i0 < ncand; i0 += PT) {
        unsigned int bx = __ldcg(&cand[i0]);
        if (((bx >> 10) & 0x7FFu) == keyB) { atomicAdd(&s_cnt[bx & 0x3FFu], 1u); atomicAdd(&s_fs[bx & 0x3FFu], __uint_as_float(bx)); }
    }
    __syncthreads();

    // ---- select-2 + tailC + finalize ----
    block_select<PT, false>(s_cnt, 1024, k2, tid, s_scan, &s_bin, &s_rem);
    __syncthreads();
    unsigned int binC = s_bin, rem = s_rem;

    float tailC = 0.0f;
    for (int i = tid; i < 1024; i += PT)
        if ((unsigned int)i > binC) tailC += s_fs[i];

    float tot = tailB + tailC;
    #pragma unroll
    for (int off = 16; off > 0; off >>= 1)
        tot += __shfl_down_sync(0xFFFFFFFFu, tot, off);
    if (lane == 0) s_wsum[tid >> 5] = tot;
    __syncthreads();
    if (tid == 0) {
        float ts = 0.0f;
        #pragma unroll
        for (int w = 0; w < PT / 32; w++) ts += s_wsum[w];
        // every value in binC has the exact bit pattern (key0<<21)|(keyB<<10)|binC
        float vstar = __uint_as_float((key0 << 21) | (keyB << 10) | binC);
        out[b] = __ldcg(&g_sum[b]) + ts + (float)rem * vstar;
    }
}

// ---------------- launch ----------------
extern "C" void kernel_launch(void* const* d_in, const int* in_sizes, int n_in,
                              void* d_out, int out_size) {
    const float* logit = (const float*)d_in[0];
    float* out = (float*)d_out;

    k_pixel<<<NPIX / 4 / 256, 256>>>(logit);
    k_region<<<dim3(IMW / TBX, IMH / TBY, BATCH), dim3(TBX, TBY)>>>();
    k_refine<<<dim3(PB, BATCH), PT>>>(out);
}

// round 16
// speedup vs baseline: 1.7154x; 1.5727x over previous
#include <cuda_runtime.h>
#include <cuda_bf16.h>
#include <cstdint>

#define BATCH 4
#define NCLS 19
#define IMH 512
#define IMW 1024
#define HW (IMH * IMW)           // 524288 = 2^19
#define NPIX (BATCH * HW)
#define KTOP 256
#define EPSF 1e-6f

// ---------------- scratch (static device arrays; no allocation) ----------------
__device__ float         g_entropy[NPIX];
__device__ unsigned char g_label[NPIX];
__device__ float         g_score[NPIX];
__device__ unsigned int  g_hist0[BATCH * 2048];
__device__ unsigned int  g_hist1[BATCH * 2048];
__device__ unsigned int  g_hist2[BATCH * 1024];
__device__ float         g_fsum [BATCH * 1024];   // per-level2-bin float sums
__device__ unsigned int  g_sel_key[BATCH];        // level-0 bin (top 11 bits)
__device__ unsigned int  g_sel_k[BATCH];          // remaining k after level 0
__device__ unsigned int  g_key01[BATCH];          // 22-bit prefix after level 1
__device__ unsigned int  g_k2[BATCH];             // remaining k after level 1
__device__ float         g_sum[BATCH];            // sum of values with 22-bit prefix > key01
__device__ unsigned int  g_ctr[3 * BATCH];        // last-block counters per phase

// ---------------- block-wide descending radix-select -------------------------
template<int T, bool LDCG>
__device__ __forceinline__ void block_select(const unsigned int* __restrict__ h,
                                             int nbins, unsigned int k, int tid,
                                             unsigned int* s_scan,      // >= T/32
                                             unsigned int* ret_bin,
                                             unsigned int* ret_rem) {
    const int W = T / 32;
    int cs = nbins / T;
    int base = nbins - 1 - tid * cs;
    unsigned int csum = 0;
    for (int i = 0; i < cs; i++) csum += LDCG ? __ldcg(&h[base - i]) : h[base - i];

    unsigned int v = csum;
    #pragma unroll
    for (int off = 1; off < 32; off <<= 1) {
        unsigned int y = __shfl_up_sync(0xFFFFFFFFu, v, off);
        if ((tid & 31) >= off) v += y;
    }
    if ((tid & 31) == 31) s_scan[tid >> 5] = v;
    __syncthreads();
    if (tid < W) {
        unsigned int w = s_scan[tid];
        const unsigned int m = (W == 32) ? 0xFFFFFFFFu : ((1u << W) - 1u);
        #pragma unroll
        for (int off = 1; off < W; off <<= 1) {
            unsigned int y = __shfl_up_sync(m, w, off);
            if (tid >= off) w += y;
        }
        s_scan[tid] = w;
    }
    __syncthreads();
    unsigned int incl = v + ((tid >= 32) ? s_scan[(tid >> 5) - 1] : 0u);
    unsigned int excl = incl - csum;

    if (excl < k && k <= incl) {
        unsigned int run = excl;
        for (int i = 0; i < cs; i++) {
            unsigned int hv = LDCG ? __ldcg(&h[base - i]) : h[base - i];
            if (run < k && k <= run + hv) {
                *ret_bin = (unsigned int)(base - i);
                *ret_rem = k - run;
                break;
            }
            run += hv;
        }
    }
}

// ---------------- kernel 1: per-pixel entropy + argmax (float4, fused init) ----
__global__ void k_pixel(const float* __restrict__ logit) {
    if (blockIdx.x == 0) {
        int t = threadIdx.x;
        for (int i = t; i < 2048 * BATCH; i += 256) { g_hist0[i] = 0; g_hist1[i] = 0; }
        for (int i = t; i < 1024 * BATCH; i += 256) { g_hist2[i] = 0; g_fsum[i] = 0.0f; }
        if (t < BATCH) { g_sel_k[t] = KTOP; g_sum[t] = 0.0f; }
        if (t < 3 * BATCH) g_ctr[t] = 0;
    }

    int idx = blockIdx.x * blockDim.x + threadIdx.x;   // one float4 (4 pixels)
    int p4 = idx * 4;
    int b  = p4 >> 19;
    int hw = p4 & (HW - 1);
    const float4* base = (const float4*)(logit + (size_t)b * NCLS * HW + hw);
    const int planeStride = HW / 4;

    float4 ent  = make_float4(0.f, 0.f, 0.f, 0.f);
    float4 best = make_float4(-1.f, -1.f, -1.f, -1.f);
    int bc0 = 0, bc1 = 0, bc2 = 0, bc3 = 0;
    #pragma unroll
    for (int c = 0; c < NCLS; c++) {
        float4 p = base[c * planeStride];
        ent.x -= p.x * __logf(p.x + EPSF);
        ent.y -= p.y * __logf(p.y + EPSF);
        ent.z -= p.z * __logf(p.z + EPSF);
        ent.w -= p.w * __logf(p.w + EPSF);
        if (p.x > best.x) { best.x = p.x; bc0 = c; }
        if (p.y > best.y) { best.y = p.y; bc1 = c; }
        if (p.z > best.z) { best.z = p.z; bc2 = c; }
        if (p.w > best.w) { best.w = p.w; bc3 = c; }
    }
    float invLogC = 1.0f / __logf((float)NCLS);
    ent.x *= invLogC; ent.y *= invLogC; ent.z *= invLogC; ent.w *= invLogC;
    ((float4*)g_entropy)[idx] = ent;
    ((uchar4*)g_label)[idx] = make_uchar4((unsigned char)bc0, (unsigned char)bc1,
                                          (unsigned char)bc2, (unsigned char)bc3);
}

// ---------------- kernel 2: 3x3 region score + hist0 + fused select0 ----------
// 256-thread block computes a 32x16 output tile (2 pixels per thread, y and y+8).
#define TBX 32
#define TBY 8
#define PY  2                       // pixels per thread in y
#define TILEY (TBY * PY + 2)        // 18 smem rows
__global__ void k_region(void) {
    __shared__ float         s_ent[TILEY][TBX + 2];
    __shared__ unsigned char s_lab[TILEY][TBX + 2];
    __shared__ unsigned int  s_hist[2048];
    __shared__ float         s_T[48];           // impurity table: [nIdx*16 + count]
    __shared__ unsigned int  s_scan[8];
    __shared__ unsigned int  s_bin, s_rem;
    __shared__ int           s_last;

    int b  = blockIdx.z;
    int bx = blockIdx.x * TBX;
    int by = blockIdx.y * (TBY * PY);
    int tx = threadIdx.x, ty = threadIdx.y;
    int tid = ty * TBX + tx;

    for (int i = tid; i < 2048; i += 256) s_hist[i] = 0;

    // impurity lookup table: T[nIdx][c] = -(c/n)*log(c/n+eps)/logC, n in {4,6,9}
    if (tid < 48) {
        int nIdx = tid >> 4, c = tid & 15;
        float n = (nIdx == 0) ? 4.0f : (nIdx == 1) ? 6.0f : 9.0f;
        float val = 0.0f;
        if (c >= 1 && c <= 9) {
            float p = (float)c / n;
            val = -p * __logf(p + EPSF) * (1.0f / __logf((float)NCLS));
        }
        s_T[tid] = val;
    }

    // halo tile load: 18 x 34
    const int TILE = TILEY * (TBX + 2);
    for (int i = tid; i < TILE; i += 256) {
        int ly = i / (TBX + 2), lx = i % (TBX + 2);
        int gy = by + ly - 1, gx = bx + lx - 1;
        bool ok = (gy >= 0 && gy < IMH && gx >= 0 && gx < IMW);
        int gidx = b * HW + gy * IMW + gx;
        s_ent[ly][lx] = ok ? g_entropy[gidx] : 0.0f;
        s_lab[ly][lx] = ok ? g_label[gidx] : (unsigned char)255;
    }
    __syncthreads();

    #pragma unroll
    for (int p = 0; p < PY; p++) {
        int ry = ty + p * TBY;              // smem row base for this pixel

        float entsum = 0.0f;
        unsigned long long accLo = 0ull;    // classes 0..15, 4-bit counters
        unsigned int accHi = 0u;            // classes 16..18
        int n = 0;
        #pragma unroll
        for (int dy = 0; dy < 3; dy++)
        #pragma unroll
            for (int dx = 0; dx < 3; dx++) {
                entsum += s_ent[ry + dy][tx + dx];
                int L = s_lab[ry + dy][tx + dx];
                if (L < 16)        { accLo += 1ull << (L * 4);        n++; }
                else if (L != 255) { accHi += 1u   << ((L - 16) * 4); n++; }
            }

        int nIdx = (n == 9) ? 2 : ((n == 6) ? 1 : 0);
        const float* T = s_T + nIdx * 16;
        float imp = 0.0f;
        #pragma unroll
        for (int c = 0; c < 16; c++) imp += T[(unsigned int)(accLo >> (c * 4)) & 15u];
        #pragma unroll
        for (int c = 0; c < 3; c++)  imp += T[(accHi >> (c * 4)) & 15u];

        float sc = entsum * (1.0f / 9.0f) * imp;
        g_score[b * HW + (by + ry) * IMW + (bx + tx)] = sc;

        unsigned int bits = __float_as_uint(sc);   // sc >= 0 => uint order == float order
        atomicAdd(&s_hist[bits >> 21], 1u);
    }
    __syncthreads();
    for (int i = tid; i < 2048; i += 256) {
        unsigned int v = s_hist[i];
        if (v) atomicAdd(&g_hist0[b * 2048 + i], v);
    }

    __threadfence();
    __syncthreads();
    if (tid == 0) {
        unsigned int done = atomicAdd(&g_ctr[0 * BATCH + b], 1u);
        s_last = (done == gridDim.x * gridDim.y - 1);
    }
    __syncthreads();
    if (s_last) {
        block_select<256, true>(g_hist0 + b * 2048, 2048, KTOP, tid,
                                s_scan, &s_bin, &s_rem);
        __syncthreads();
        if (tid == 0) { g_sel_key[b] = s_bin; g_sel_k[b] = s_rem; }
    }
}

// ---------------- kernel 3: level-1 histogram + fused select1 -----------------
#define RB 128   // blocks per batch
#define RT 512   // threads per block
__global__ void k_refine1(void) {
    __shared__ unsigned int s_hist[2048];
    __shared__ unsigned int s_scan[RT / 32];
    __shared__ unsigned int s_bin, s_rem;
    __shared__ int s_last;

    int b = blockIdx.y;
    int tid = threadIdx.x;
    unsigned int key0 = g_sel_key[b];
    const float4* sc = (const float4*)(g_score + b * HW);

    for (int i = tid; i < 2048; i += RT) s_hist[i] = 0;
    __syncthreads();

    const int TPB = RB * RT;                 // 65536
    const int ITER = (HW / 4) / TPB;         // 2
    int start = blockIdx.x * RT + tid;
    #pragma unroll
    for (int it = 0; it < ITER; it++) {
        float4 v = sc[start + it * TPB];
        unsigned int bx;
        bx = __float_as_uint(v.x); if ((bx >> 21) == key0) atomicAdd(&s_hist[(bx >> 10) & 0x7FFu], 1u);
        bx = __float_as_uint(v.y); if ((bx >> 21) == key0) atomicAdd(&s_hist[(bx >> 10) & 0x7FFu], 1u);
        bx = __float_as_uint(v.z); if ((bx >> 21) == key0) atomicAdd(&s_hist[(bx >> 10) & 0x7FFu], 1u);
        bx = __float_as_uint(v.w); if ((bx >> 21) == key0) atomicAdd(&s_hist[(bx >> 10) & 0x7FFu], 1u);
    }
    __syncthreads();
    for (int i = tid; i < 2048; i += RT) {
        unsigned int v = s_hist[i];
        if (v) atomicAdd(&g_hist1[b * 2048 + i], v);
    }

    __threadfence();
    __syncthreads();
    if (tid == 0) {
        unsigned int done = atomicAdd(&g_ctr[1 * BATCH + b], 1u);
        s_last = (done == gridDim.x - 1);
    }
    __syncthreads();
    if (s_last) {
        block_select<RT, true>(g_hist1 + b * 2048, 2048, g_sel_k[b], tid,
                               s_scan, &s_bin, &s_rem);
        __syncthreads();
        if (tid == 0) {
            g_key01[b] = (key0 << 11) | s_bin;   // 22-bit prefix
            g_k2[b]    = s_rem;
        }
    }
}

// ---------------- kernel 4: level-2 count+sum histogram + fused finalize ------
__global__ void k_refine2(float* __restrict__ out) {
    __shared__ unsigned int s_cnt[1024];
    __shared__ float        s_fs[1024];
    __shared__ unsigned int s_scan[RT / 32];
    __shared__ float        s_wsum[RT / 32];
    __shared__ unsigned int s_bin, s_rem;
    __shared__ int s_last;

    int b = blockIdx.y;
    int tid = threadIdx.x;
    int lane = tid & 31;
    unsigned int key01 = g_key01[b];
    const float4* sc = (const float4*)(g_score + b * HW);

    for (int i = tid; i < 1024; i += RT) { s_cnt[i] = 0; s_fs[i] = 0.0f; }
    __syncthreads();

    float gsum = 0.0f;
    const int TPB = RB * RT;
    const int ITER = (HW / 4) / TPB;
    int start = blockIdx.x * RT + tid;
    #pragma unroll
    for (int it = 0; it < ITER; it++) {
        float4 v = sc[start + it * TPB];
        float val[4] = { v.x, v.y, v.z, v.w };
        #pragma unroll
        for (int j = 0; j < 4; j++) {
            unsigned int bits = __float_as_uint(val[j]);
            unsigned int pref = bits >> 10;
            if (pref > key01) gsum += val[j];
            else if (pref == key01) {
                unsigned int bin = bits & 0x3FFu;
                atomicAdd(&s_cnt[bin], 1u);
                atomicAdd(&s_fs[bin], val[j]);
            }
        }
    }

    // block reduce gsum -> global
    #pragma unroll
    for (int off = 16; off > 0; off >>= 1)
        gsum += __shfl_down_sync(0xFFFFFFFFu, gsum, off);
    if (lane == 0) s_wsum[tid >> 5] = gsum;
    __syncthreads();
    if (tid == 0) {
        float bs = 0.0f;
        #pragma unroll
        for (int w = 0; w < RT / 32; w++) bs += s_wsum[w];
        if (bs != 0.0f) atomicAdd(&g_sum[b], bs);
    }
    __syncthreads();
    for (int i = tid; i < 1024; i += RT) {
        unsigned int c = s_cnt[i];
        if (c) { atomicAdd(&g_hist2[b * 1024 + i], c); atomicAdd(&g_fsum[b * 1024 + i], s_fs[i]); }
    }

    __threadfence();
    __syncthreads();
    if (tid == 0) {
        unsigned int done = atomicAdd(&g_ctr[2 * BATCH + b], 1u);
        s_last = (done == gridDim.x - 1);
    }
    __syncthreads();
    if (!s_last) return;

    // ---- last block: select level 2 + closed-form finalize ----
    unsigned int k2 = g_k2[b];
    block_select<RT, true>(g_hist2 + b * 1024, 1024, k2, tid, s_scan, &s_bin, &s_rem);
    __syncthreads();
    unsigned int binstar = s_bin, rem = s_rem;

    // sum of per-bin float sums for bins strictly above binstar
    float tail = 0.0f;
    for (int i = tid; i < 1024; i += RT)
        if ((unsigned int)i > binstar) tail += __ldcg(&g_fsum[b * 1024 + i]);
    #pragma unroll
    for (int off = 16; off > 0; off >>= 1)
        tail += __shfl_down_sync(0xFFFFFFFFu, tail, off);
    if (lane == 0) s_wsum[tid >> 5] = tail;
    __syncthreads();
    if (tid == 0) {
        float ts = 0.0f;
        #pragma unroll
        for (int w = 0; w < RT / 32; w++) ts += s_wsum[w];
        // every value in binstar has the exact bit pattern (key01<<10)|binstar
        float vstar = __uint_as_float((key01 << 10) | binstar);
        out[b] = __ldcg(&g_sum[b]) + ts + (float)rem * vstar;
    }
}

// ---------------- launch ----------------
extern "C" void kernel_launch(void* const* d_in, const int* in_sizes, int n_in,
                              void* d_out, int out_size) {
    const float* logit = (const float*)d_in[0];
    float* out = (float*)d_out;

    k_pixel<<<NPIX / 4 / 256, 256>>>(logit);
    k_region<<<dim3(IMW / TBX, IMH / (TBY * PY), BATCH), dim3(TBX, TBY)>>>();
    k_refine1<<<dim3(RB, BATCH), RT>>>();
    k_refine2<<<dim3(RB, BATCH), RT>>>(out);
}

// round 17
// speedup vs baseline: 1.7546x; 1.0228x over previous
#include <cuda_runtime.h>
#include <cuda_bf16.h>
#include <cstdint>

#define BATCH 4
#define NCLS 19
#define IMH 512
#define IMW 1024
#define HW (IMH * IMW)           // 524288 = 2^19
#define NPIX (BATCH * HW)
#define KTOP 256
#define EPSF 1e-6f

// ---------------- scratch (static device arrays; no allocation) ----------------
__device__ float         g_entropy[NPIX];
__device__ unsigned char g_label[NPIX];
__device__ float         g_score[NPIX];
__device__ unsigned int  g_hist0[BATCH * 2048];
__device__ unsigned int  g_hist1[BATCH * 2048];
__device__ unsigned int  g_hist2[BATCH * 1024];
__device__ float         g_fsum [BATCH * 1024];   // per-level2-bin float sums
__device__ unsigned int  g_sel_key[BATCH];        // level-0 bin (top 11 bits)
__device__ unsigned int  g_sel_k[BATCH];          // remaining k after level 0
__device__ unsigned int  g_key01[BATCH];          // 22-bit prefix after level 1
__device__ unsigned int  g_k2[BATCH];             // remaining k after level 1
__device__ float         g_sum[BATCH];            // sum of values with 22-bit prefix > key01
__device__ unsigned int  g_ctr[3 * BATCH];        // last-block counters per phase

// ---------------- block-wide descending radix-select -------------------------
template<int T, bool LDCG>
__device__ __forceinline__ void block_select(const unsigned int* __restrict__ h,
                                             int nbins, unsigned int k, int tid,
                                             unsigned int* s_scan,      // >= T/32
                                             unsigned int* ret_bin,
                                             unsigned int* ret_rem) {
    const int W = T / 32;
    int cs = nbins / T;
    int base = nbins - 1 - tid * cs;
    unsigned int csum = 0;
    for (int i = 0; i < cs; i++) csum += LDCG ? __ldcg(&h[base - i]) : h[base - i];

    unsigned int v = csum;
    #pragma unroll
    for (int off = 1; off < 32; off <<= 1) {
        unsigned int y = __shfl_up_sync(0xFFFFFFFFu, v, off);
        if ((tid & 31) >= off) v += y;
    }
    if ((tid & 31) == 31) s_scan[tid >> 5] = v;
    __syncthreads();
    if (tid < W) {
        unsigned int w = s_scan[tid];
        const unsigned int m = (W == 32) ? 0xFFFFFFFFu : ((1u << W) - 1u);
        #pragma unroll
        for (int off = 1; off < W; off <<= 1) {
            unsigned int y = __shfl_up_sync(m, w, off);
            if (tid >= off) w += y;
        }
        s_scan[tid] = w;
    }
    __syncthreads();
    unsigned int incl = v + ((tid >= 32) ? s_scan[(tid >> 5) - 1] : 0u);
    unsigned int excl = incl - csum;

    if (excl < k && k <= incl) {
        unsigned int run = excl;
        for (int i = 0; i < cs; i++) {
            unsigned int hv = LDCG ? __ldcg(&h[base - i]) : h[base - i];
            if (run < k && k <= run + hv) {
                *ret_bin = (unsigned int)(base - i);
                *ret_rem = k - run;
                break;
            }
            run += hv;
        }
    }
}

// ---------------- kernel 1: per-pixel entropy + argmax (float4, fused init) ----
__global__ void k_pixel(const float* __restrict__ logit) {
    if (blockIdx.x == 0) {
        int t = threadIdx.x;
        for (int i = t; i < 2048 * BATCH; i += 256) { g_hist0[i] = 0; g_hist1[i] = 0; }
        for (int i = t; i < 1024 * BATCH; i += 256) { g_hist2[i] = 0; g_fsum[i] = 0.0f; }
        if (t < BATCH) { g_sel_k[t] = KTOP; g_sum[t] = 0.0f; }
        if (t < 3 * BATCH) g_ctr[t] = 0;
    }

    int idx = blockIdx.x * blockDim.x + threadIdx.x;   // one float4 (4 pixels)
    int p4 = idx * 4;
    int b  = p4 >> 19;
    int hw = p4 & (HW - 1);
    const float4* base = (const float4*)(logit + (size_t)b * NCLS * HW + hw);
    const int planeStride = HW / 4;

    float4 ent  = make_float4(0.f, 0.f, 0.f, 0.f);
    float4 best = make_float4(-1.f, -1.f, -1.f, -1.f);
    int bc0 = 0, bc1 = 0, bc2 = 0, bc3 = 0;
    #pragma unroll
    for (int c = 0; c < NCLS; c++) {
        float4 p = base[c * planeStride];
        ent.x -= p.x * __logf(p.x + EPSF);
        ent.y -= p.y * __logf(p.y + EPSF);
        ent.z -= p.z * __logf(p.z + EPSF);
        ent.w -= p.w * __logf(p.w + EPSF);
        if (p.x > best.x) { best.x = p.x; bc0 = c; }
        if (p.y > best.y) { best.y = p.y; bc1 = c; }
        if (p.z > best.z) { best.z = p.z; bc2 = c; }
        if (p.w > best.w) { best.w = p.w; bc3 = c; }
    }
    float invLogC = 1.0f / __logf((float)NCLS);
    ent.x *= invLogC; ent.y *= invLogC; ent.z *= invLogC; ent.w *= invLogC;
    ((float4*)g_entropy)[idx] = ent;
    ((uchar4*)g_label)[idx] = make_uchar4((unsigned char)bc0, (unsigned char)bc1,
                                          (unsigned char)bc2, (unsigned char)bc3);
}

// ---------------- kernel 2: 3x3 region score + hist0 + fused select0 ----------
// 256-thread block computes a 32x16 output tile (2 pixels per thread, y and y+8).
#define TBX 32
#define TBY 8
#define PY  2                       // pixels per thread in y
#define TILEY (TBY * PY + 2)        // 18 smem rows
__global__ void k_region(void) {
    __shared__ float         s_ent[TILEY][TBX + 2];
    __shared__ unsigned char s_lab[TILEY][TBX + 2];
    __shared__ unsigned int  s_hist[2048];
    __shared__ float         s_T[48];           // impurity table: [nIdx*16 + count]
    __shared__ unsigned int  s_scan[8];
    __shared__ unsigned int  s_bin, s_rem;
    __shared__ int           s_last;

    int b  = blockIdx.z;
    int bx = blockIdx.x * TBX;
    int by = blockIdx.y * (TBY * PY);
    int tx = threadIdx.x, ty = threadIdx.y;
    int tid = ty * TBX + tx;
    int lane = tid & 31;

    for (int i = tid; i < 2048; i += 256) s_hist[i] = 0;

    // impurity lookup table: T[nIdx][c] = -(c/n)*log(c/n+eps)/logC, n in {4,6,9}
    if (tid < 48) {
        int nIdx = tid >> 4, c = tid & 15;
        float n = (nIdx == 0) ? 4.0f : (nIdx == 1) ? 6.0f : 9.0f;
        float val = 0.0f;
        if (c >= 1 && c <= 9) {
            float p = (float)c / n;
            val = -p * __logf(p + EPSF) * (1.0f / __logf((float)NCLS));
        }
        s_T[tid] = val;
    }

    // halo tile load: 18 x 34
    const int TILE = TILEY * (TBX + 2);
    for (int i = tid; i < TILE; i += 256) {
        int ly = i / (TBX + 2), lx = i % (TBX + 2);
        int gy = by + ly - 1, gx = bx + lx - 1;
        bool ok = (gy >= 0 && gy < IMH && gx >= 0 && gx < IMW);
        int gidx = b * HW + gy * IMW + gx;
        s_ent[ly][lx] = ok ? g_entropy[gidx] : 0.0f;
        s_lab[ly][lx] = ok ? g_label[gidx] : (unsigned char)255;
    }
    __syncthreads();

    #pragma unroll
    for (int p = 0; p < PY; p++) {
        int ry = ty + p * TBY;              // smem row base for this pixel

        float entsum = 0.0f;
        unsigned long long accLo = 0ull;    // classes 0..15, 4-bit counters
        unsigned int accHi = 0u;            // classes 16..18
        int n = 0;
        #pragma unroll
        for (int dy = 0; dy < 3; dy++)
        #pragma unroll
            for (int dx = 0; dx < 3; dx++) {
                entsum += s_ent[ry + dy][tx + dx];
                int L = s_lab[ry + dy][tx + dx];
                if (L < 16)        { accLo += 1ull << (L * 4);        n++; }
                else if (L != 255) { accHi += 1u   << ((L - 16) * 4); n++; }
            }

        int nIdx = (n == 9) ? 2 : ((n == 6) ? 1 : 0);
        const float* T = s_T + nIdx * 16;
        float imp = 0.0f;
        #pragma unroll
        for (int c = 0; c < 16; c++) imp += T[(unsigned int)(accLo >> (c * 4)) & 15u];
        #pragma unroll
        for (int c = 0; c < 3; c++)  imp += T[(accHi >> (c * 4)) & 15u];

        float sc = entsum * (1.0f / 9.0f) * imp;
        g_score[b * HW + (by + ry) * IMW + (bx + tx)] = sc;

        // warp-aggregated hist0 atomic (scores concentrated -> hot bins)
        unsigned int bits = __float_as_uint(sc);   // sc >= 0 => uint order == float order
        unsigned int bin = bits >> 21;
        unsigned int peers = __match_any_sync(0xFFFFFFFFu, bin);
        if (lane == __ffs(peers) - 1)
            atomicAdd(&s_hist[bin], (unsigned int)__popc(peers));
    }
    __syncthreads();
    for (int i = tid; i < 2048; i += 256) {
        unsigned int v = s_hist[i];
        if (v) atomicAdd(&g_hist0[b * 2048 + i], v);
    }

    __threadfence();
    __syncthreads();
    if (tid == 0) {
        unsigned int done = atomicAdd(&g_ctr[0 * BATCH + b], 1u);
        s_last = (done == gridDim.x * gridDim.y - 1);
    }
    __syncthreads();
    if (s_last) {
        block_select<256, true>(g_hist0 + b * 2048, 2048, KTOP, tid,
                                s_scan, &s_bin, &s_rem);
        __syncthreads();
        if (tid == 0) { g_sel_key[b] = s_bin; g_sel_k[b] = s_rem; }
    }
}

// ---------------- kernel 3: level-1 histogram + fused select1 -----------------
// RB=64 blocks/batch, 4 independent float4 loads hoisted per thread (MLP=4).
#define RB 64    // blocks per batch
#define RT 512   // threads per block
__global__ void k_refine1(void) {
    __shared__ unsigned int s_hist[2048];
    __shared__ unsigned int s_scan[RT / 32];
    __shared__ unsigned int s_bin, s_rem;
    __shared__ int s_last;

    int b = blockIdx.y;
    int tid = threadIdx.x;
    unsigned int key0 = g_sel_key[b];
    const float4* sc = (const float4*)(g_score + b * HW);

    for (int i = tid; i < 2048; i += RT) s_hist[i] = 0;
    __syncthreads();

    const int TPB = RB * RT;                 // 32768
    int start = blockIdx.x * RT + tid;
    // 4 independent loads, front-batched for MLP
    float4 v0 = sc[start];
    float4 v1 = sc[start + TPB];
    float4 v2 = sc[start + 2 * TPB];
    float4 v3 = sc[start + 3 * TPB];

    float vals[16] = { v0.x, v0.y, v0.z, v0.w, v1.x, v1.y, v1.z, v1.w,
                       v2.x, v2.y, v2.z, v2.w, v3.x, v3.y, v3.z, v3.w };
    #pragma unroll
    for (int j = 0; j < 16; j++) {
        unsigned int bx = __float_as_uint(vals[j]);
        if ((bx >> 21) == key0) atomicAdd(&s_hist[(bx >> 10) & 0x7FFu], 1u);
    }
    __syncthreads();
    for (int i = tid; i < 2048; i += RT) {
        unsigned int v = s_hist[i];
        if (v) atomicAdd(&g_hist1[b * 2048 + i], v);
    }

    __threadfence();
    __syncthreads();
    if (tid == 0) {
        unsigned int done = atomicAdd(&g_ctr[1 * BATCH + b], 1u);
        s_last = (done == gridDim.x - 1);
    }
    __syncthreads();
    if (s_last) {
        block_select<RT, true>(g_hist1 + b * 2048, 2048, g_sel_k[b], tid,
                               s_scan, &s_bin, &s_rem);
        __syncthreads();
        if (tid == 0) {
            g_key01[b] = (key0 << 11) | s_bin;   // 22-bit prefix
            g_k2[b]    = s_rem;
        }
    }
}

// ---------------- kernel 4: level-2 count+sum histogram + fused finalize ------
__global__ void k_refine2(float* __restrict__ out) {
    __shared__ unsigned int s_cnt[1024];
    __shared__ float        s_fs[1024];
    __shared__ unsigned int s_scan[RT / 32];
    __shared__ float        s_wsum[RT / 32];
    __shared__ unsigned int s_bin, s_rem;
    __shared__ int s_last;

    int b = blockIdx.y;
    int tid = threadIdx.x;
    int lane = tid & 31;
    unsigned int key01 = g_key01[b];
    const float4* sc = (const float4*)(g_score + b * HW);

    for (int i = tid; i < 1024; i += RT) { s_cnt[i] = 0; s_fs[i] = 0.0f; }
    __syncthreads();

    const int TPB = RB * RT;                 // 32768
    int start = blockIdx.x * RT + tid;
    float4 v0 = sc[start];
    float4 v1 = sc[start + TPB];
    float4 v2 = sc[start + 2 * TPB];
    float4 v3 = sc[start + 3 * TPB];

    float vals[16] = { v0.x, v0.y, v0.z, v0.w, v1.x, v1.y, v1.z, v1.w,
                       v2.x, v2.y, v2.z, v2.w, v3.x, v3.y, v3.z, v3.w };
    float gsum = 0.0f;
    #pragma unroll
    for (int j = 0; j < 16; j++) {
        unsigned int bits = __float_as_uint(vals[j]);
        unsigned int pref = bits >> 10;
        if (pref > key01) gsum += vals[j];
        else if (pref == key01) {
            unsigned int bin = bits & 0x3FFu;
            atomicAdd(&s_cnt[bin], 1u);
            atomicAdd(&s_fs[bin], vals[j]);
        }
    }

    // block reduce gsum -> global
    #pragma unroll
    for (int off = 16; off > 0; off >>= 1)
        gsum += __shfl_down_sync(0xFFFFFFFFu, gsum, off);
    if (lane == 0) s_wsum[tid >> 5] = gsum;
    __syncthreads();
    if (tid == 0) {
        float bs = 0.0f;
        #pragma unroll
        for (int w = 0; w < RT / 32; w++) bs += s_wsum[w];
        if (bs != 0.0f) atomicAdd(&g_sum[b], bs);
    }
    __syncthreads();
    for (int i = tid; i < 1024; i += RT) {
        unsigned int c = s_cnt[i];
        if (c) { atomicAdd(&g_hist2[b * 1024 + i], c); atomicAdd(&g_fsum[b * 1024 + i], s_fs[i]); }
    }

    __threadfence();
    __syncthreads();
    if (tid == 0) {
        unsigned int done = atomicAdd(&g_ctr[2 * BATCH + b], 1u);
        s_last = (done == gridDim.x - 1);
    }
    __syncthreads();
    if (!s_last) return;

    // ---- last block: select level 2 + closed-form finalize ----
    unsigned int k2 = g_k2[b];
    block_select<RT, true>(g_hist2 + b * 1024, 1024, k2, tid, s_scan, &s_bin, &s_rem);
    __syncthreads();
    unsigned int binstar = s_bin, rem = s_rem;

    // sum of per-bin float sums for bins strictly above binstar
    float tail = 0.0f;
    for (int i = tid; i < 1024; i += RT)
        if ((unsigned int)i > binstar) tail += __ldcg(&g_fsum[b * 1024 + i]);
    #pragma unroll
    for (int off = 16; off > 0; off >>= 1)
        tail += __shfl_down_sync(0xFFFFFFFFu, tail, off);
    if (lane == 0) s_wsum[tid >> 5] = tail;
    __syncthreads();
    if (tid == 0) {
        float ts = 0.0f;
        #pragma unroll
        for (int w = 0; w < RT / 32; w++) ts += s_wsum[w];
        // every value in binstar has the exact bit pattern (key01<<10)|binstar
        float vstar = __uint_as_float((key01 << 10) | binstar);
        out[b] = __ldcg(&g_sum[b]) + ts + (float)rem * vstar;
    }
}

// ---------------- launch ----------------
extern "C" void kernel_launch(void* const* d_in, const int* in_sizes, int n_in,
                              void* d_out, int out_size) {
    const float* logit = (const float*)d_in[0];
    float* out = (float*)d_out;

    k_pixel<<<NPIX / 4 / 256, 256>>>(logit);
    k_region<<<dim3(IMW / TBX, IMH / (TBY * PY), BATCH), dim3(TBX, TBY)>>>();
    k_refine1<<<dim3(RB, BATCH), RT>>>();
    k_refine2<<<dim3(RB, BATCH), RT>>>(out);
}